// round 10
// baseline (speedup 1.0000x reference)
#include <cuda_runtime.h>
#include <math.h>

#define NIMG 16
#define NCLS 80
#define NREF 256
#define SCAP 8192       // smem candidate cap
#define SLCAP 2048      // smem seglist cap
#define THWPAD 20480
#define NSEG 6480       // segments per image (class-aligned 256-chunks)
#define NSEGPAD 6528

#define MAGICF 12582912.0f              // 1.5 * 2^23 : round-to-nearest-int magic
#define KC (127 - 0x4B400000)           // exponent rebias for magic-rounded y
#define C1F 0.70710678f                 // quad minimax of 2^f on [-0.5, 0.5]
#define C2F 0.24264069f

// dynamic smem: cand(64K) + sbuf(16K) + hist(32K) + seglist(8K) = 120KB
#define SMEM_SEL (65536 + 16384 + 32768 + 8192)

typedef unsigned long long u64;

// ---------------- scratch (device globals; no allocs) ----------------
__device__ float g_ctrD[NIMG * THWPAD];             // (1 + e^{-ctr}), padded layout
__device__ float g_segD[NIMG * NSEGPAD];            // per-segment min D

struct P5 { const float* lg[5]; const float* rg[5]; const float* ct[5]; const float* lc[5]; };

__constant__ int c_HW[5]   = {15200, 3800, 950, 247, 70};
__constant__ int c_hwb2[5] = {0, 15232, 19072, 20032, 20288};  // 16B-aligned bases
__constant__ int c_rb[5]   = {0, 1216000, 1520000, 1596000, 1615760};
__constant__ float c_str[5] = {8.f, 16.f, 32.f, 64.f, 128.f};

// ---- packed f32x2 helpers (Blackwell PTX) ----
__device__ __forceinline__ u64 pk2(float lo, float hi) {
    u64 r; asm("mov.b64 %0,{%1,%2};" : "=l"(r) : "f"(lo), "f"(hi)); return r;
}
__device__ __forceinline__ void upk2(u64 v, float& lo, float& hi) {
    asm("mov.b64 {%0,%1},%2;" : "=f"(lo), "=f"(hi) : "l"(v));
}
__device__ __forceinline__ u64 mul2(u64 a, u64 b) {
    u64 r; asm("mul.rn.f32x2 %0,%1,%2;" : "=l"(r) : "l"(a), "l"(b)); return r;
}
__device__ __forceinline__ u64 add2(u64 a, u64 b) {
    u64 r; asm("add.rn.f32x2 %0,%1,%2;" : "=l"(r) : "l"(a), "l"(b)); return r;
}
__device__ __forceinline__ u64 fma2(u64 a, u64 b, u64 c) {
    u64 r; asm("fma.rn.f32x2 %0,%1,%2,%3;" : "=l"(r) : "l"(a), "l"(b), "l"(c)); return r;
}

// Scalar surrogate e^{-x}: magic-round exp2 split + quad minimax. Contraction-proof
// (__fmul_rn/__fadd_rn/fmaf) so it is BITWISE identical to the packed f32x2 path.
__device__ __forceinline__ float expneg_s(float x) {
    float u = __fmul_rn(-1.44269504f, x);
    float y = __fadd_rn(u, MAGICF);
    int iy = __float_as_int(y);
    float yf = __fadd_rn(y, -MAGICF);
    float f = fmaf(yf, -1.0f, u);
    float pm = fmaf(fmaf(C2F, f, C1F), f, 1.0f);
    float sc = __int_as_float((iy + KC) << 23);
    return __fmul_rn(pm, sc);
}

// surrogate inverse-score key, NO gate (gated elems have D>20 >> cut ~2-4)
__device__ __forceinline__ float Dkey_s(float a, float cd) {
    return fmaf(expneg_s(a), cd, cd);             // (1 + e^-a) * cd
}

// Reference-exact sigmoid (libdevice expf == XLA f32 exp), survivors only.
__device__ __forceinline__ float sig_ref(float x) {
    return 1.0f / (1.0f + expf(-x));
}

struct Seg { int l, c, hw0, HW; };
__device__ __forceinline__ Seg seg_decode(int wid) {
    Seg s;
    if (wid < 4800)      { s.l=0; s.c=wid/60;  s.hw0=(wid-s.c*60)<<8;  s.HW=15200; }
    else if (wid < 6000) { int t=wid-4800; s.l=1; s.c=t/15; s.hw0=(t-s.c*15)<<8; s.HW=3800; }
    else if (wid < 6320) { int t=wid-6000; s.l=2; s.c=t>>2; s.hw0=(t&3)<<8; s.HW=950; }
    else if (wid < 6400) { s.l=3; s.c=wid-6320; s.hw0=0; s.HW=247; }
    else                 { s.l=4; s.c=wid-6400; s.hw0=0; s.HW=70; }
    return s;
}

__global__ void k_ctr(P5 p) {
    int i = blockIdx.x * blockDim.x + threadIdx.x;
    if (i >= NIMG * THWPAD) return;
    int n = i / THWPAD, g = i - n * THWPAD;
    int l, hw;
    if (g < 15200)                     { l = 0; hw = g; }
    else if (g >= 15232 && g < 19032)  { l = 1; hw = g - 15232; }
    else if (g >= 19072 && g < 20022)  { l = 2; hw = g - 19072; }
    else if (g >= 20032 && g < 20279)  { l = 3; hw = g - 20032; }
    else if (g >= 20288 && g < 20358)  { l = 4; hw = g - 20288; }
    else return;
    g_ctrD[i] = __fadd_rn(1.0f, expneg_s(p.ct[l][n * c_HW[l] + hw]));
}

// full pass: per-segment (256-elem) min of surrogate D. Packed f32x2 math for
// levels 0/1 (16B-aligned rows, 94% of data); scalar for levels 2-4 + tails.
__global__ void k_minred(P5 p) {
    int n = blockIdx.y;
    int wid = blockIdx.x * 8 + (threadIdx.x >> 5);
    int lane = threadIdx.x & 31;
    if (wid >= NSEG) return;
    Seg sg = seg_decode(wid);
    const float* lg = p.lg[sg.l] + ((size_t)n * NCLS + sg.c) * sg.HW;
    const float* cd = g_ctrD + n * THWPAD + c_hwb2[sg.l];
    int base = sg.hw0 + lane * 8;
    float m = 3.4e38f;
    if (sg.l < 2 && base + 8 <= sg.HW) {
        float4 a0 = *(const float4*)(lg + base);
        float4 a1 = *(const float4*)(lg + base + 4);
        float4 d0 = *(const float4*)(cd + base);
        float4 d1 = *(const float4*)(cd + base + 4);
        u64 A[4] = {pk2(a0.x,a0.y), pk2(a0.z,a0.w), pk2(a1.x,a1.y), pk2(a1.z,a1.w)};
        u64 C[4] = {pk2(d0.x,d0.y), pk2(d0.z,d0.w), pk2(d1.x,d1.y), pk2(d1.z,d1.w)};
        const u64 NL2  = pk2(-1.44269504f, -1.44269504f);
        const u64 MG   = pk2(MAGICF, MAGICF);
        const u64 NMG  = pk2(-MAGICF, -MAGICF);
        const u64 NONE2= pk2(-1.0f, -1.0f);
        const u64 C2P  = pk2(C2F, C2F);
        const u64 C1P  = pk2(C1F, C1F);
        const u64 ONE2 = pk2(1.0f, 1.0f);
        #pragma unroll
        for (int i = 0; i < 4; i++) {
            u64 u  = mul2(A[i], NL2);
            u64 y  = add2(u, MG);
            float ylo, yhi; upk2(y, ylo, yhi);
            u64 yf = add2(y, NMG);
            u64 f  = fma2(yf, NONE2, u);
            u64 pm = fma2(fma2(C2P, f, C1P), f, ONE2);
            float slo = __int_as_float((__float_as_int(ylo) + KC) << 23);
            float shi = __int_as_float((__float_as_int(yhi) + KC) << 23);
            u64 e  = mul2(pm, pk2(slo, shi));
            u64 D  = fma2(e, C[i], C[i]);
            float dlo, dhi; upk2(D, dlo, dhi);
            m = fminf(m, fminf(dlo, dhi));
        }
    } else {
        #pragma unroll
        for (int k = 0; k < 8; k++) {
            int h = base + k;
            if (h < sg.HW) m = fminf(m, Dkey_s(lg[h], cd[h]));
        }
    }
    #pragma unroll
    for (int o = 16; o; o >>= 1) m = fminf(m, __shfl_xor_sync(0xffffffffu, m, o));
    if (lane == 0) g_segD[n * NSEGPAD + wid] = m;
}

__device__ __forceinline__ void push_s(u64* cand, int* hist, int* ccnt, int n,
                                       float a, float cv, int rnk) {
    float sa = sig_ref(a);
    if (sa > 0.05f) {                           // exact reference gate
        float v = sa * sig_ref(cv);
        if (v > 0.0f) {
            int pos = atomicAdd(ccnt, 1);
            if (pos < SCAP) {
                unsigned vb = __float_as_uint(v);
                cand[pos] = ((u64)vb << 32) | (0x7FFFFFFFu - (unsigned)rnk);
                atomicAdd(&hist[vb >> 19], 1);
            }
        }
    }
}

// ONE block per image: cut -> seglist -> compact -> rank-select -> sort -> out
__global__ void __launch_bounds__(1024) k_select(P5 p, float* out) {
    extern __shared__ char sm[];
    u64* cand = (u64*)sm;                       // 8192 u64  (64KB)
    u64* sbuf = (u64*)(sm + 65536);             // 2048 u64  (16KB)
    int* hist = (int*)(sm + 65536 + 16384);     // 8192 int  (32KB)
    int* sgl  = (int*)(sm + 65536 + 16384 + 32768); // 2048 int (8KB)
    __shared__ int wtot[32], wpre[32];
    __shared__ int ccnt, lcnt, bres, bsel, mcnt;
    int n = blockIdx.x, tid = threadIdx.x;
    const int nt = 1024;
    int lane = tid & 31, w = tid >> 5;

    // ---- Phase A: segD histogram (4096 buckets) + ascending rank-select ----
    for (int i = tid; i < 4096; i += nt) hist[i] = 0;
    if (tid == 0) { ccnt = 0; lcnt = 0; bres = 4095; bsel = 0; mcnt = 0; }
    __syncthreads();
    for (int i = tid; i < NSEG; i += nt) {
        unsigned b = __float_as_uint(g_segD[n * NSEGPAD + i]) >> 19;
        atomicAdd(&hist[min(b, 4095u)], 1);
    }
    __syncthreads();
    {
        int s4 = hist[tid*4] + hist[tid*4+1] + hist[tid*4+2] + hist[tid*4+3];
        int pre = s4;
        #pragma unroll
        for (int o = 1; o < 32; o <<= 1) {
            int t2 = __shfl_up_sync(0xffffffffu, pre, o);
            if (lane >= o) pre += t2;
        }
        if (lane == 31) wtot[w] = pre;
        __syncthreads();
        if (tid < 32) {
            int v = wtot[tid];
            int s = v;
            #pragma unroll
            for (int o = 1; o < 32; o <<= 1) {
                int t2 = __shfl_up_sync(0xffffffffu, s, o);
                if (tid >= o) s += t2;
            }
            wpre[tid] = s - v;
        }
        __syncthreads();
        int excl = wpre[w] + (pre - s4);
        if (excl < NREF && excl + s4 >= NREF) {
            int cum = excl;
            #pragma unroll
            for (int b = 0; b < 4; b++) {
                cum += hist[tid*4 + b];
                if (cum >= NREF) { bres = tid*4 + b; break; }
            }
        }
    }
    __syncthreads();
    int bc = min(bres + 1, 4095);       // +1 bucket: surrogate-vs-exact slop

    // ---- Phase B: build seglist in smem ----
    for (int i = tid; i < NSEG; i += nt) {
        unsigned b = __float_as_uint(g_segD[n * NSEGPAD + i]) >> 19;
        if ((int)b <= bc) {
            int pos = atomicAdd(&lcnt, 1);
            if (pos < SLCAP) sgl[pos] = i;
        }
    }
    __syncthreads();
    int lc = min(lcnt, SLCAP);
    for (int i = tid; i < 8192; i += nt) hist[i] = 0;   // re-zero for score hist
    __syncthreads();

    // ---- Phase C: compact (flattened quad loop over listed segments) ----
    int total = lc << 6;                 // 64 quads per 256-elem segment
    for (int e = tid; e < total; e += nt) {
        int si = sgl[e >> 6];
        Seg sg = seg_decode(si);
        int hw = sg.hw0 + ((e & 63) << 2);
        const float* lg = p.lg[sg.l] + ((size_t)n * NCLS + sg.c) * sg.HW;
        const float* cd = g_ctrD + n * THWPAD + c_hwb2[sg.l];
        const float* ctp = p.ct[sg.l] + (size_t)n * sg.HW;
        int rb = c_rb[sg.l];
        if (sg.l < 2 && hw + 4 <= sg.HW) {
            float4 a = *(const float4*)(lg + hw);
            float4 d = *(const float4*)(cd + hw);
            float aa[4] = {a.x, a.y, a.z, a.w};
            float dd[4] = {d.x, d.y, d.z, d.w};
            #pragma unroll
            for (int k = 0; k < 4; k++)
                if ((int)(__float_as_uint(Dkey_s(aa[k], dd[k])) >> 19) <= bc)
                    push_s(cand, hist, &ccnt, n, aa[k], ctp[hw+k],
                           rb + (hw+k) * NCLS + sg.c);
        } else {
            #pragma unroll
            for (int k = 0; k < 4; k++) {
                int h = hw + k;
                if (h < sg.HW) {
                    float a = lg[h];
                    if ((int)(__float_as_uint(Dkey_s(a, cd[h])) >> 19) <= bc)
                        push_s(cand, hist, &ccnt, n, a, ctp[h],
                               rb + h * NCLS + sg.c);
                }
            }
        }
    }
    __syncthreads();
    int cnt = min(ccnt, SCAP);

    // ---- Phase D: descending rank-select over 8192 score buckets ----
    {
        int s8 = 0;
        #pragma unroll
        for (int j = 0; j < 8; j++) s8 += hist[tid*8 + j];
        int suf = s8;
        #pragma unroll
        for (int o = 1; o < 32; o <<= 1) {
            int t2 = __shfl_down_sync(0xffffffffu, suf, o);
            if (lane + o < 32) suf += t2;
        }
        if (lane == 0) wtot[w] = suf;
        __syncthreads();
        if (tid < 32) {
            int v = wtot[tid];
            int s = v;
            #pragma unroll
            for (int o = 1; o < 32; o <<= 1) {
                int t2 = __shfl_down_sync(0xffffffffu, s, o);
                if (tid + o < 32) s += t2;
            }
            wpre[tid] = s - v;           // exclusive suffix over warps above
        }
        __syncthreads();
        int above = wpre[w] + (suf - s8);
        if (above < NREF && above + s8 >= NREF) {
            int cum = above;
            #pragma unroll
            for (int b = 7; b >= 0; b--) {
                cum += hist[tid*8 + b];
                if (cum >= NREF) { bsel = tid*8 + b; break; }
            }
        }
    }
    __syncthreads();
    int bs2 = bsel;

    // ---- filter to sbuf, pad, adaptive bitonic sort ----
    for (int i = tid; i < cnt; i += nt) {
        u64 kk = cand[i];
        if ((int)(kk >> 51) >= bs2) {
            int pos = atomicAdd(&mcnt, 1);
            if (pos < 2048) sbuf[pos] = kk;
        }
    }
    __syncthreads();
    int mm = min(mcnt, 2048);
    int S = (mm <= 512) ? 512 : 2048;
    for (int i = tid; i < S; i += nt) if (i >= mm) sbuf[i] = 0ULL;
    __syncthreads();
    for (int k = 2; k <= S; k <<= 1) {
        for (int j = k >> 1; j > 0; j >>= 1) {
            for (int i = tid; i < S; i += nt) {
                int ixj = i ^ j;
                if (ixj > i) {
                    u64 x = sbuf[i], y = sbuf[ixj];
                    bool desc = ((i & k) == 0);
                    if (desc ? (x < y) : (x > y)) { sbuf[i] = y; sbuf[ixj] = x; }
                }
            }
            __syncthreads();
        }
    }

    // ---- output ----
    if (tid < NREF) {
        u64 kk = sbuf[tid];
        float sc = 0.f, x0 = 0.f, y0 = 0.f, x1 = 0.f, y1 = 0.f;
        int cls = 0, lvl = 0;
        if (kk) {
            float v = __uint_as_float((unsigned)(kk >> 32));
            unsigned rank = 0x7FFFFFFFu - (unsigned)(kk & 0xFFFFFFFFu);
            int l;
            if (rank < 1216000u) l = 0;
            else if (rank < 1520000u) l = 1;
            else if (rank < 1596000u) l = 2;
            else if (rank < 1615760u) l = 3;
            else l = 4;
            int HWl = c_HW[l];
            int r = (int)rank - c_rb[l];
            int loc = r / NCLS;
            cls = r - NCLS * loc;
            lvl = l;
            float strf = c_str[l];
            float px = p.lc[l][2 * loc], py = p.lc[l][2 * loc + 1];
            const float* rg = p.rg[l] + (size_t)n * 4 * HWl;
            float r0 = rg[loc] * strf;
            float r1 = rg[HWl + loc] * strf;
            float r2 = rg[2 * HWl + loc] * strf;
            float r3 = rg[3 * HWl + loc] * strf;
            sc = sqrtf(v);
            x0 = px - r0; y0 = py - r1; x1 = px + r2; y1 = py + r3;
        }
        int o = n * NREF + tid;
        out[o] = sc;
        float* ob = out + NIMG * NREF;
        ob[o * 4 + 0] = x0; ob[o * 4 + 1] = y0;
        ob[o * 4 + 2] = x1; ob[o * 4 + 3] = y1;
        float* oc = out + NIMG * NREF * 5;
        oc[o] = (float)cls;
        float* ol = out + NIMG * NREF * 6;
        ol[o] = (float)lvl;
    }
}

extern "C" void kernel_launch(void* const* d_in, const int* in_sizes, int n_in,
                              void* d_out, int out_size) {
    P5 p;
    for (int l = 0; l < 5; l++) {
        p.lg[l] = (const float*)d_in[4 * l + 0];
        p.rg[l] = (const float*)d_in[4 * l + 1];
        p.ct[l] = (const float*)d_in[4 * l + 2];
        p.lc[l] = (const float*)d_in[4 * l + 3];
    }
    cudaFuncSetAttribute(k_select, cudaFuncAttributeMaxDynamicSharedMemorySize,
                         SMEM_SEL);
    k_ctr<<<(NIMG * THWPAD + 255) / 256, 256>>>(p);
    dim3 g(810, NIMG);       // 810*8 warps >= 6480 segments
    k_minred<<<g, 256>>>(p);
    k_select<<<NIMG, 1024, SMEM_SEL>>>(p, (float*)d_out);
}

// round 11
// speedup vs baseline: 1.3738x; 1.3738x over previous
#include <cuda_runtime.h>
#include <math.h>

#define NIMG 16
#define NCLS 80
#define NREF 256
#define CAP  8192
#define LCAP 8192
#define THWPAD 20480
#define NSEG 6480       // segments per image (class-aligned 256-chunks)
#define NSEGPAD 6528

#define MAGICF 12582912.0f              // 1.5 * 2^23 : round-to-nearest-int magic
#define KC (127 - 0x4B400000)           // exponent rebias for magic-rounded y
#define C1F 0.70710678f                 // quad minimax of 2^f on [-0.5, 0.5]
#define C2F 0.24264069f

typedef unsigned long long u64;

// ---------------- scratch (device globals; no allocs) ----------------
__device__ float g_ctrD[NIMG * THWPAD];             // (1 + e^{-ctr}), padded layout
__device__ float g_segD[NIMG * NSEGPAD];            // per-segment min D
__device__ int   g_bcut[NIMG];
__device__ int   g_cnt[NIMG];
__device__ int   g_lcnt[NIMG];
__device__ int   g_seglist[NIMG][LCAP];
__device__ unsigned long long g_cand[NIMG][CAP];

struct P5 { const float* lg[5]; const float* rg[5]; const float* ct[5]; const float* lc[5]; };

__constant__ int c_HW[5]   = {15200, 3800, 950, 247, 70};
__constant__ int c_hwb2[5] = {0, 15232, 19072, 20032, 20288};  // 16B-aligned bases
__constant__ int c_rb[5]   = {0, 1216000, 1520000, 1596000, 1615760};
__constant__ float c_str[5] = {8.f, 16.f, 32.f, 64.f, 128.f};

// ---- packed f32x2 helpers (Blackwell PTX) ----
__device__ __forceinline__ u64 pk2(float lo, float hi) {
    u64 r; asm("mov.b64 %0,{%1,%2};" : "=l"(r) : "f"(lo), "f"(hi)); return r;
}
__device__ __forceinline__ void upk2(u64 v, float& lo, float& hi) {
    asm("mov.b64 {%0,%1},%2;" : "=f"(lo), "=f"(hi) : "l"(v));
}
__device__ __forceinline__ u64 mul2(u64 a, u64 b) {
    u64 r; asm("mul.rn.f32x2 %0,%1,%2;" : "=l"(r) : "l"(a), "l"(b)); return r;
}
__device__ __forceinline__ u64 add2(u64 a, u64 b) {
    u64 r; asm("add.rn.f32x2 %0,%1,%2;" : "=l"(r) : "l"(a), "l"(b)); return r;
}
__device__ __forceinline__ u64 fma2(u64 a, u64 b, u64 c) {
    u64 r; asm("fma.rn.f32x2 %0,%1,%2,%3;" : "=l"(r) : "l"(a), "l"(b), "l"(c)); return r;
}

// Scalar surrogate e^{-x}: magic-round exp2 split + quad minimax. Contraction-proof
// (__fmul_rn/__fadd_rn/fmaf) so it is BITWISE identical to the packed f32x2 path.
// MUST stay in sync with the packed sequence in k_minred.
__device__ __forceinline__ float expneg_s(float x) {
    float u = __fmul_rn(-1.44269504f, x);
    float y = __fadd_rn(u, MAGICF);
    int iy = __float_as_int(y);
    float yf = __fadd_rn(y, -MAGICF);
    float f = fmaf(yf, -1.0f, u);
    float pm = fmaf(fmaf(C2F, f, C1F), f, 1.0f);
    float sc = __int_as_float((iy + KC) << 23);
    return __fmul_rn(pm, sc);
}

// surrogate inverse-score key, NO gate (gated elems have D>20 >> cut ~2-4)
__device__ __forceinline__ float Dkey_s(float a, float cd) {
    return fmaf(expneg_s(a), cd, cd);             // (1 + e^-a) * cd
}

// Reference-exact sigmoid (libdevice expf == XLA f32 exp), survivors only.
__device__ __forceinline__ float sig_ref(float x) {
    return 1.0f / (1.0f + expf(-x));
}

struct Seg { int l, c, hw0, HW; };
__device__ __forceinline__ Seg seg_decode(int wid) {
    Seg s;
    if (wid < 4800)      { s.l=0; s.c=wid/60;  s.hw0=(wid-s.c*60)<<8;  s.HW=15200; }
    else if (wid < 6000) { int t=wid-4800; s.l=1; s.c=t/15; s.hw0=(t-s.c*15)<<8; s.HW=3800; }
    else if (wid < 6320) { int t=wid-6000; s.l=2; s.c=t>>2; s.hw0=(t&3)<<8; s.HW=950; }
    else if (wid < 6400) { s.l=3; s.c=wid-6320; s.hw0=0; s.HW=247; }
    else                 { s.l=4; s.c=wid-6400; s.hw0=0; s.HW=70; }
    return s;
}

__global__ void k_ctr(P5 p) {
    int i = blockIdx.x * blockDim.x + threadIdx.x;
    if (i < NIMG) { g_cnt[i] = 0; g_lcnt[i] = 0; }
    if (i >= NIMG * THWPAD) return;
    int n = i / THWPAD, g = i - n * THWPAD;
    int l, hw;
    if (g < 15200)                     { l = 0; hw = g; }
    else if (g >= 15232 && g < 19032)  { l = 1; hw = g - 15232; }
    else if (g >= 19072 && g < 20022)  { l = 2; hw = g - 19072; }
    else if (g >= 20032 && g < 20279)  { l = 3; hw = g - 20032; }
    else if (g >= 20288 && g < 20358)  { l = 4; hw = g - 20288; }
    else return;
    g_ctrD[i] = __fadd_rn(1.0f, expneg_s(p.ct[l][n * c_HW[l] + hw]));
}

// full pass: per-segment (256-elem) min of surrogate D. Packed f32x2 math for
// levels 0/1 (16B-aligned rows, 94% of data); scalar for levels 2-4 + tails.
__global__ void k_minred(P5 p) {
    int n = blockIdx.y;
    int wid = blockIdx.x * 8 + (threadIdx.x >> 5);
    int lane = threadIdx.x & 31;
    if (wid >= NSEG) return;
    Seg sg = seg_decode(wid);
    const float* lg = p.lg[sg.l] + ((size_t)n * NCLS + sg.c) * sg.HW;
    const float* cd = g_ctrD + n * THWPAD + c_hwb2[sg.l];
    int base = sg.hw0 + lane * 8;
    float m = 3.4e38f;
    if (sg.l < 2 && base + 8 <= sg.HW) {
        float4 a0 = *(const float4*)(lg + base);
        float4 a1 = *(const float4*)(lg + base + 4);
        float4 d0 = *(const float4*)(cd + base);
        float4 d1 = *(const float4*)(cd + base + 4);
        u64 A[4] = {pk2(a0.x,a0.y), pk2(a0.z,a0.w), pk2(a1.x,a1.y), pk2(a1.z,a1.w)};
        u64 C[4] = {pk2(d0.x,d0.y), pk2(d0.z,d0.w), pk2(d1.x,d1.y), pk2(d1.z,d1.w)};
        const u64 NL2  = pk2(-1.44269504f, -1.44269504f);
        const u64 MG   = pk2(MAGICF, MAGICF);
        const u64 NMG  = pk2(-MAGICF, -MAGICF);
        const u64 NONE2= pk2(-1.0f, -1.0f);
        const u64 C2P  = pk2(C2F, C2F);
        const u64 C1P  = pk2(C1F, C1F);
        const u64 ONE2 = pk2(1.0f, 1.0f);
        #pragma unroll
        for (int i = 0; i < 4; i++) {
            u64 u  = mul2(A[i], NL2);
            u64 y  = add2(u, MG);
            float ylo, yhi; upk2(y, ylo, yhi);
            u64 yf = add2(y, NMG);
            u64 f  = fma2(yf, NONE2, u);
            u64 pm = fma2(fma2(C2P, f, C1P), f, ONE2);
            float slo = __int_as_float((__float_as_int(ylo) + KC) << 23);
            float shi = __int_as_float((__float_as_int(yhi) + KC) << 23);
            u64 e  = mul2(pm, pk2(slo, shi));
            u64 D  = fma2(e, C[i], C[i]);
            float dlo, dhi; upk2(D, dlo, dhi);
            m = fminf(m, fminf(dlo, dhi));
        }
    } else {
        #pragma unroll
        for (int k = 0; k < 8; k++) {
            int h = base + k;
            if (h < sg.HW) m = fminf(m, Dkey_s(lg[h], cd[h]));
        }
    }
    #pragma unroll
    for (int o = 16; o; o >>= 1) m = fminf(m, __shfl_xor_sync(0xffffffffu, m, o));
    if (lane == 0) g_segD[n * NSEGPAD + wid] = m;
}

// ascending rank-select over 4096 buckets of seg-mins, then build seglist
__global__ void __launch_bounds__(512) k_cut() {
    __shared__ int hist[4096];
    __shared__ int wtot[16], wpre[16];
    __shared__ int bres;
    int n = blockIdx.x, tid = threadIdx.x, nt = blockDim.x;
    int lane = tid & 31, w = tid >> 5;
    for (int i = tid; i < 4096; i += nt) hist[i] = 0;
    if (tid == 0) bres = 4095;
    __syncthreads();
    for (int i = tid; i < NSEG; i += nt) {
        unsigned b = __float_as_uint(g_segD[n * NSEGPAD + i]) >> 19;
        atomicAdd(&hist[min(b, 4095u)], 1);
    }
    __syncthreads();
    int s8 = 0;
    #pragma unroll
    for (int j = 0; j < 8; j++) s8 += hist[tid * 8 + j];
    int pre = s8;
    #pragma unroll
    for (int o = 1; o < 32; o <<= 1) {
        int t2 = __shfl_up_sync(0xffffffffu, pre, o);
        if (lane >= o) pre += t2;
    }
    if (lane == 31) wtot[w] = pre;
    __syncthreads();
    if (tid < 16) {
        int v = wtot[tid];
        int s = v;
        #pragma unroll
        for (int o = 1; o < 16; o <<= 1) {
            int t2 = __shfl_up_sync(0xffffu, s, o);
            if (tid >= o) s += t2;
        }
        wpre[tid] = s - v;
    }
    __syncthreads();
    int excl = wpre[w] + (pre - s8);
    if (excl < NREF && excl + s8 >= NREF) {
        int cum = excl;
        #pragma unroll
        for (int b = 0; b < 8; b++) {
            cum += hist[tid * 8 + b];
            if (cum >= NREF) { bres = tid * 8 + b; break; }
        }
    }
    __syncthreads();
    int bc = min(bres + 1, 4095);       // +1 bucket: surrogate-vs-exact slop
    if (tid == 0) g_bcut[n] = bc;
    for (int i = tid; i < NSEG; i += nt) {
        unsigned b = __float_as_uint(g_segD[n * NSEGPAD + i]) >> 19;
        if ((int)b <= bc) {
            int pos = atomicAdd(&g_lcnt[n], 1);
            if (pos < LCAP) g_seglist[n][pos] = i;
        }
    }
}

__device__ __forceinline__ void push_cand(int n, float a, float ctr_v, int rnk) {
    float sa = sig_ref(a);
    if (sa > 0.05f) {                           // exact reference gate
        float v = sa * sig_ref(ctr_v);
        if (v > 0.0f) {
            unsigned long long kk =
                ((unsigned long long)__float_as_uint(v) << 32) |
                (0x7FFFFFFFu - (unsigned)rnk);
            int pos = atomicAdd(&g_cnt[n], 1);
            if (pos < CAP) g_cand[n][pos] = kk;
        }
    }
}

// flattened: one float4-quad per thread over all listed segments -> latency
// is overlapped across 64K threads/image instead of serialized within warps
__global__ void k_compact(P5 p) {
    int n = blockIdx.y;
    int bcut = g_bcut[n];
    int lcnt = min(g_lcnt[n], LCAP);
    int total = lcnt << 6;              // 64 quads per 256-elem segment
    int stride = gridDim.x * blockDim.x;
    for (int e = blockIdx.x * blockDim.x + threadIdx.x; e < total; e += stride) {
        int si = g_seglist[n][e >> 6];
        Seg sg = seg_decode(si);
        int hw = sg.hw0 + ((e & 63) << 2);
        const float* lg = p.lg[sg.l] + ((size_t)n * NCLS + sg.c) * sg.HW;
        const float* cd = g_ctrD + n * THWPAD + c_hwb2[sg.l];
        const float* ctp = p.ct[sg.l] + (size_t)n * sg.HW;
        int rb = c_rb[sg.l];
        if (sg.l < 2 && hw + 4 <= sg.HW) {
            float4 a = *(const float4*)(lg + hw);
            float4 d = *(const float4*)(cd + hw);
            float aa[4] = {a.x, a.y, a.z, a.w};
            float dd[4] = {d.x, d.y, d.z, d.w};
            #pragma unroll
            for (int k = 0; k < 4; k++)
                if ((int)(__float_as_uint(Dkey_s(aa[k], dd[k])) >> 19) <= bcut)
                    push_cand(n, aa[k], ctp[hw + k], rb + (hw + k) * NCLS + sg.c);
        } else {
            #pragma unroll
            for (int k = 0; k < 4; k++) {
                int h = hw + k;
                if (h < sg.HW) {
                    float a = lg[h];
                    if ((int)(__float_as_uint(Dkey_s(a, cd[h])) >> 19) <= bcut)
                        push_cand(n, a, ctp[h], rb + h * NCLS + sg.c);
                }
            }
        }
    }
}

__global__ void __launch_bounds__(1024) k_sort(P5 p, float* out) {
    __shared__ union { int hist[8192]; unsigned long long buf[2048]; } u;  // 32KB
    __shared__ int wtot[32], wsuf[32];
    __shared__ int m, bs;
    int n = blockIdx.x, tid = threadIdx.x, nt = blockDim.x;
    int lane = tid & 31, w = tid >> 5;
    int cnt = min(g_cnt[n], CAP);
    for (int i = tid; i < 8192; i += nt) u.hist[i] = 0;
    if (tid == 0) { m = 0; bs = 0; }
    __syncthreads();

    for (int i = tid; i < cnt; i += nt)
        atomicAdd(&u.hist[(int)(g_cand[n][i] >> 51)], 1);
    __syncthreads();

    // hierarchical descending rank-select over 8192 buckets
    int s8 = 0;
    #pragma unroll
    for (int j = 0; j < 8; j++) s8 += u.hist[tid * 8 + j];
    int suf = s8;
    #pragma unroll
    for (int o = 1; o < 32; o <<= 1) {
        int t2 = __shfl_down_sync(0xffffffffu, suf, o);
        if (lane + o < 32) suf += t2;
    }
    if (lane == 0) wtot[w] = suf;
    __syncthreads();
    if (tid < 32) {
        int v = wtot[tid];
        int s = v;
        #pragma unroll
        for (int o = 1; o < 32; o <<= 1) {
            int t2 = __shfl_down_sync(0xffffffffu, s, o);
            if (tid + o < 32) s += t2;
        }
        wsuf[tid] = s - v;
    }
    __syncthreads();
    int above = wsuf[w] + (suf - s8);
    if (above < NREF && above + s8 >= NREF) {
        int cum = above;
        #pragma unroll
        for (int b = 7; b >= 0; b--) {
            cum += u.hist[tid * 8 + b];
            if (cum >= NREF) { bs = tid * 8 + b; break; }
        }
    }
    __syncthreads();
    int bcut2 = bs;
    __syncthreads();                     // hist dead; buf overlay safe

    for (int i = tid; i < cnt; i += nt) {
        unsigned long long kk = g_cand[n][i];
        if ((int)(kk >> 51) >= bcut2) {
            int pos = atomicAdd(&m, 1);
            if (pos < 2048) u.buf[pos] = kk;
        }
    }
    __syncthreads();
    int mm = min(m, 2048);
    int S = (mm <= 512) ? 512 : 2048;    // adaptive sort width (m is ~256+eps)
    for (int i = tid; i < S; i += nt) if (i >= mm) u.buf[i] = 0ULL;
    __syncthreads();

    // bitonic sort descending; keys unique (rank embedded) -> deterministic
    for (int k = 2; k <= S; k <<= 1) {
        for (int j = k >> 1; j > 0; j >>= 1) {
            for (int i = tid; i < S; i += nt) {
                int ixj = i ^ j;
                if (ixj > i) {
                    unsigned long long x = u.buf[i], y = u.buf[ixj];
                    bool desc = ((i & k) == 0);
                    if (desc ? (x < y) : (x > y)) { u.buf[i] = y; u.buf[ixj] = x; }
                }
            }
            __syncthreads();
        }
    }

    if (tid < NREF) {
        unsigned long long kk = u.buf[tid];
        float sc = 0.f, x0 = 0.f, y0 = 0.f, x1 = 0.f, y1 = 0.f;
        int cls = 0, lvl = 0;
        if (kk) {
            float v = __uint_as_float((unsigned)(kk >> 32));
            unsigned rank = 0x7FFFFFFFu - (unsigned)(kk & 0xFFFFFFFFu);
            int l;
            if (rank < 1216000u) l = 0;
            else if (rank < 1520000u) l = 1;
            else if (rank < 1596000u) l = 2;
            else if (rank < 1615760u) l = 3;
            else l = 4;
            int HWl = c_HW[l];
            int r = (int)rank - c_rb[l];
            int loc = r / NCLS;
            cls = r - NCLS * loc;
            lvl = l;
            float strf = c_str[l];
            float px = p.lc[l][2 * loc], py = p.lc[l][2 * loc + 1];
            const float* rg = p.rg[l] + (size_t)n * 4 * HWl;
            float r0 = rg[loc] * strf;
            float r1 = rg[HWl + loc] * strf;
            float r2 = rg[2 * HWl + loc] * strf;
            float r3 = rg[3 * HWl + loc] * strf;
            sc = sqrtf(v);
            x0 = px - r0; y0 = py - r1; x1 = px + r2; y1 = py + r3;
        }
        int o = n * NREF + tid;
        out[o] = sc;
        float* ob = out + NIMG * NREF;
        ob[o * 4 + 0] = x0; ob[o * 4 + 1] = y0;
        ob[o * 4 + 2] = x1; ob[o * 4 + 3] = y1;
        float* oc = out + NIMG * NREF * 5;
        oc[o] = (float)cls;
        float* ol = out + NIMG * NREF * 6;
        ol[o] = (float)lvl;
    }
}

extern "C" void kernel_launch(void* const* d_in, const int* in_sizes, int n_in,
                              void* d_out, int out_size) {
    P5 p;
    for (int l = 0; l < 5; l++) {
        p.lg[l] = (const float*)d_in[4 * l + 0];
        p.rg[l] = (const float*)d_in[4 * l + 1];
        p.ct[l] = (const float*)d_in[4 * l + 2];
        p.lc[l] = (const float*)d_in[4 * l + 3];
    }
    k_ctr<<<(NIMG * THWPAD + 255) / 256, 256>>>(p);
    dim3 g(810, NIMG);       // 810*8 warps >= 6480 segments
    k_minred<<<g, 256>>>(p);
    k_cut<<<NIMG, 512>>>();
    dim3 gc(256, NIMG);      // 64K threads/image, ~1 quad per thread
    k_compact<<<gc, 256>>>(p);
    k_sort<<<NIMG, 1024>>>(p, (float*)d_out);
}